// round 4
// baseline (speedup 1.0000x reference)
#include <cuda_runtime.h>
#include <stdint.h>

// Inputs (metadata order):
//   d_in[0] disp        float32 [E,3]   (E = 3,200,000)
//   d_in[1] a           float32 [E]
//   d_in[2] b           float32 [E]
//   d_in[3] edge_index  int32   [2,E]   row0 = src, row1 = dst  (JAX x64 off -> int32)
//   d_in[4] atom_node   int32   [N]     (only N matters; N = 100,000)
// Output: float32 [N,3]
//
// Math: r2 = |disp|^2 ; E = sum a*r2 + b*exp(-r2)
//       force_edge = -dE/ddisp = 2*(b*exp(-r2) - a) * disp
//       out = segsum(force, src) - segsum(force, dst)

__global__ void zero_out_kernel(float4* __restrict__ out, int n4) {
    int i = blockIdx.x * blockDim.x + threadIdx.x;
    if (i < n4) out[i] = make_float4(0.f, 0.f, 0.f, 0.f);
}

__global__ __launch_bounds__(256)
void edge_force_scatter_kernel(const float* __restrict__ disp,
                               const float* __restrict__ a,
                               const float* __restrict__ b,
                               const int* __restrict__ src,
                               const int* __restrict__ dst,
                               float* __restrict__ out,
                               int num_edges) {
    int e = blockIdx.x * blockDim.x + threadIdx.x;
    if (e >= num_edges) return;

    float dx = disp[3 * e + 0];
    float dy = disp[3 * e + 1];
    float dz = disp[3 * e + 2];
    float r2 = fmaf(dx, dx, fmaf(dy, dy, dz * dz));

    float ae = a[e];
    float be = b[e];
    // scale = 2*(b*exp(-r2) - a)
    float s = 2.0f * fmaf(be, __expf(-r2), -ae);

    float fx = s * dx;
    float fy = s * dy;
    float fz = s * dz;

    int si = src[e];
    int di = dst[e];
    float* po = out + 3 * si;
    float* qo = out + 3 * di;

    atomicAdd(po + 0,  fx);
    atomicAdd(po + 1,  fy);
    atomicAdd(po + 2,  fz);
    atomicAdd(qo + 0, -fx);
    atomicAdd(qo + 1, -fy);
    atomicAdd(qo + 2, -fz);
}

extern "C" void kernel_launch(void* const* d_in, const int* in_sizes, int n_in,
                              void* d_out, int out_size) {
    const float* disp = (const float*)d_in[0];
    const float* a    = (const float*)d_in[1];
    const float* b    = (const float*)d_in[2];
    const int*   ei   = (const int*)d_in[3];   // int32 [2, E]

    int num_edges = in_sizes[1];               // a is [E]
    const int* src = ei;
    const int* dst = ei + num_edges;

    float* out = (float*)d_out;

    // Zero-init output (poisoned to 0xAA by the harness). 300000 % 4 == 0.
    int n4 = out_size / 4;
    {
        int threads = 256;
        int blocks = (n4 + threads - 1) / threads;
        zero_out_kernel<<<blocks, threads>>>((float4*)out, n4);
    }

    {
        int threads = 256;
        int blocks = (num_edges + threads - 1) / threads;
        edge_force_scatter_kernel<<<blocks, threads>>>(disp, a, b, src, dst,
                                                       out, num_edges);
    }
}

// round 5
// speedup vs baseline: 2.4281x; 2.4281x over previous
#include <cuda_runtime.h>
#include <stdint.h>

// Inputs (metadata order):
//   d_in[0] disp        float32 [E,3]   (E = 3,200,000)
//   d_in[1] a           float32 [E]
//   d_in[2] b           float32 [E]
//   d_in[3] edge_index  int32   [2,E]   row0 = src, row1 = dst
//   d_in[4] atom_node   int32   [N]     (N = 100,000)
// Output: float32 [N,3]
//
// force_edge = 2*(b*exp(-r2) - a) * disp ;  out = scatter(+,src) - scatter(+,dst)
//
// Strategy: accumulate into a padded [N,4] float4 scratch with native
// sm_90+ float4 atomicAdd (2 RED ops/edge instead of 6), then compact to [N,3].

#define N_MAX 100352  // >= 100000, padded

__device__ float4 g_accum[N_MAX];

__global__ void zero_scratch_kernel(int n) {
    int i = blockIdx.x * blockDim.x + threadIdx.x;
    if (i < n) g_accum[i] = make_float4(0.f, 0.f, 0.f, 0.f);
}

__global__ __launch_bounds__(256)
void edge_force_scatter_kernel(const float* __restrict__ disp,
                               const float* __restrict__ a,
                               const float* __restrict__ b,
                               const int* __restrict__ src,
                               const int* __restrict__ dst,
                               int num_edges) {
    int e = blockIdx.x * blockDim.x + threadIdx.x;
    if (e >= num_edges) return;

    float dx = disp[3 * e + 0];
    float dy = disp[3 * e + 1];
    float dz = disp[3 * e + 2];
    float r2 = fmaf(dx, dx, fmaf(dy, dy, dz * dz));

    float ae = a[e];
    float be = b[e];
    float s = 2.0f * fmaf(be, __expf(-r2), -ae);  // 2*(b*exp(-r2) - a)

    float fx = s * dx;
    float fy = s * dy;
    float fz = s * dz;

    int si = src[e];
    int di = dst[e];

    atomicAdd(&g_accum[si], make_float4( fx,  fy,  fz, 0.f));
    atomicAdd(&g_accum[di], make_float4(-fx, -fy, -fz, 0.f));
}

__global__ void gather_out_kernel(float* __restrict__ out, int n) {
    int i = blockIdx.x * blockDim.x + threadIdx.x;
    if (i < n) {
        float4 v = g_accum[i];
        out[3 * i + 0] = v.x;
        out[3 * i + 1] = v.y;
        out[3 * i + 2] = v.z;
    }
}

extern "C" void kernel_launch(void* const* d_in, const int* in_sizes, int n_in,
                              void* d_out, int out_size) {
    const float* disp = (const float*)d_in[0];
    const float* a    = (const float*)d_in[1];
    const float* b    = (const float*)d_in[2];
    const int*   ei   = (const int*)d_in[3];   // int32 [2, E]

    int num_edges = in_sizes[1];               // a is [E]
    const int* src = ei;
    const int* dst = ei + num_edges;

    float* out = (float*)d_out;
    int n_atoms = out_size / 3;

    {
        int threads = 256;
        int blocks = (n_atoms + threads - 1) / threads;
        zero_scratch_kernel<<<blocks, threads>>>(n_atoms);
    }
    {
        int threads = 256;
        int blocks = (num_edges + threads - 1) / threads;
        edge_force_scatter_kernel<<<blocks, threads>>>(disp, a, b, src, dst,
                                                       num_edges);
    }
    {
        int threads = 256;
        int blocks = (n_atoms + threads - 1) / threads;
        gather_out_kernel<<<blocks, threads>>>(out, n_atoms);
    }
}